// round 12
// baseline (speedup 1.0000x reference)
#include <cuda_runtime.h>
#include <cuda_bf16.h>
#include <math.h>
#include <stdint.h>

#define BATCH_N 32768
#define IN_DIM  1024
#define ATTN_D  128
#define OUT_D   1024
#define NHEADS  8

#define KT      32
#define PADE    40                 /* bf16 elems per smem row (32 data + 8 pad) */
#define ROWB    (PADE * 2)         /* 80 bytes per row */
#define TILE_B  (128 * ROWB)       /* 10240 bytes */
#define BUF_B   (4 * TILE_B)       /* Ahi, Alo, Bhi, Blo = 40960 */
#define NSTAGE  3
#define SMEM_BUFS (NSTAGE * BUF_B)         /* 122880 */
#define ATTN_OFF  SMEM_BUFS                /* 4KB: attnS (MODE2) / sdot (MODE1) */
#define ACCT_OFF  (SMEM_BUFS + 4096)       /* 64KB: accT (MODE2 only) */
#define SMEM_T01  (SMEM_BUFS + 4096)
#define SMEM_T2   (ACCT_OFF + 65536)       /* 192512 */

// ---------------- device-global scratch (no cudaMalloc allowed) --------
__device__ float g_q[(size_t)BATCH_N * ATTN_D];
__device__ float g_dot[BATCH_N * NHEADS];
__device__ float g_attn[BATCH_N * NHEADS];
__device__ uint2 g_xhi[(size_t)BATCH_N * IN_DIM / 4];
__device__ uint2 g_xlo[(size_t)BATCH_N * IN_DIM / 4];
__device__ uint2 g_wqhi[ATTN_D * IN_DIM / 4];
__device__ uint2 g_wqlo[ATTN_D * IN_DIM / 4];
__device__ uint2 g_wkhi[NHEADS * ATTN_D * IN_DIM / 4];
__device__ uint2 g_wklo[NHEADS * ATTN_D * IN_DIM / 4];
__device__ uint2 g_wvhi[(size_t)NHEADS * OUT_D * IN_DIM / 4];
__device__ uint2 g_wvlo[(size_t)NHEADS * OUT_D * IN_DIM / 4];

__device__ __forceinline__ unsigned smem_u32(const void* p) {
    return (unsigned)__cvta_generic_to_shared(p);
}

// fp32x4 -> (4 bf16 hi, 4 bf16 lo residual) packed as uint2 each
__device__ __forceinline__ void split4(float4 v, uint2& hi, uint2& lo) {
    __nv_bfloat162 h01 = __floats2bfloat162_rn(v.x, v.y);
    __nv_bfloat162 h23 = __floats2bfloat162_rn(v.z, v.w);
    float r0 = v.x - __bfloat162float(h01.x);
    float r1 = v.y - __bfloat162float(h01.y);
    float r2 = v.z - __bfloat162float(h23.x);
    float r3 = v.w - __bfloat162float(h23.y);
    __nv_bfloat162 l01 = __floats2bfloat162_rn(r0, r1);
    __nv_bfloat162 l23 = __floats2bfloat162_rn(r2, r3);
    hi.x = *(unsigned*)&h01; hi.y = *(unsigned*)&h23;
    lo.x = *(unsigned*)&l01; lo.y = *(unsigned*)&l23;
}

__global__ void split_kernel(const float4* __restrict__ src, uint2* __restrict__ hi,
                             uint2* __restrict__ lo, int n4) {
    int i = blockIdx.x * blockDim.x + threadIdx.x;
    if (i < n4) {
        uint2 h, l;
        split4(src[i], h, l);
        hi[i] = h; lo[i] = l;
    }
}

__device__ __forceinline__ void ldsm_x4(unsigned* r, unsigned addr) {
    asm volatile("ldmatrix.sync.aligned.m8n8.x4.shared.b16 {%0,%1,%2,%3}, [%4];"
                 : "=r"(r[0]), "=r"(r[1]), "=r"(r[2]), "=r"(r[3]) : "r"(addr));
}
__device__ __forceinline__ void mma_bf16(float* d, const unsigned* a, const unsigned* b) {
    asm volatile(
        "mma.sync.aligned.m16n8k16.row.col.f32.bf16.bf16.f32 "
        "{%0,%1,%2,%3}, {%4,%5,%6,%7}, {%8,%9}, {%0,%1,%2,%3};"
        : "+f"(d[0]), "+f"(d[1]), "+f"(d[2]), "+f"(d[3])
        : "r"(a[0]), "r"(a[1]), "r"(a[2]), "r"(a[3]), "r"(b[0]), "r"(b[1]));
}

#define CP16(sm, gp) asm volatile("cp.async.cg.shared.global [%0], [%1], 16;" \
                                  :: "r"(sm), "l"(gp) : "memory")
#define CP_COMMIT()  asm volatile("cp.async.commit_group;" ::: "memory")
#define CP_WAIT1()   asm volatile("cp.async.wait_group 1;" ::: "memory")

// MODE 0: Q gemm (N=128)             out=g_q
// MODE 1: K gemm + q.k dot epilogue  out=g_dot, aux=g_q
// MODE 2: V gemm, per-head smem merge out=d_out, aux=g_attn  (NKT=256)
template <int MODE, int NKT>
__global__ void __launch_bounds__(256, 1)
gemm_kernel(const char* __restrict__ Ahi, const char* __restrict__ Alo,
            const char* __restrict__ Bhi, const char* __restrict__ Blo,
            const float* __restrict__ bias, const float* __restrict__ aux,
            float* __restrict__ out) {
    extern __shared__ char smem[];
    const unsigned sbase = smem_u32(smem);
    const int tid  = threadIdx.x;
    const int warp = tid >> 5, lane = tid & 31;
    const int bm = blockIdx.x;
    const int bn = blockIdx.y;
    const int rowBase = bm * 128;
    const int bRowBase = (MODE == 0) ? 0 : bn * 128;

    float* attnS = (float*)(smem + ATTN_OFF);   // MODE 2: 128x8
    float* sdot  = (float*)(smem + ATTN_OFF);   // MODE 1: 128 floats
    float* accT  = (float*)(smem + ACCT_OFF);   // MODE 2: [64][256]

    if (MODE == 1) { if (tid < 128) sdot[tid] = 0.f; }
    if (MODE == 2) {
        for (int i = tid; i < 128 * NHEADS; i += 256)
            attnS[i] = aux[(size_t)(rowBase + (i >> 3)) * NHEADS + (i & 7)];
#pragma unroll
        for (int i = 0; i < 64; i++) accT[i * 256 + tid] = 0.f;  // thread-private slots
    }

    // per-thread copy slots: 2 chunks of 16B per tile
    const int row0 = tid >> 2,          c0 = tid & 3;
    const int row1 = (tid + 256) >> 2,  c1 = (tid + 256) & 3;
    const size_t aOff0 = ((size_t)(rowBase + row0) * IN_DIM + c0 * 8) * 2;
    const size_t aOff1 = ((size_t)(rowBase + row1) * IN_DIM + c1 * 8) * 2;
    const size_t bOff0 = ((size_t)(bRowBase + row0) * IN_DIM + c0 * 8) * 2;
    const size_t bOff1 = ((size_t)(bRowBase + row1) * IN_DIM + c1 * 8) * 2;
    const unsigned sm0 = row0 * ROWB + c0 * 16;
    const unsigned sm1 = row1 * ROWB + c1 * 16;

    auto LOAD = [&](int s, int bi) {
        if (s < NKT) {
            const unsigned sb = sbase + bi * BUF_B;
            const size_t ka = (size_t)((s * KT) & (IN_DIM - 1)) * 2;
            const size_t kb = (MODE == 2)
                ? ka + (size_t)(s >> 5) * ((size_t)OUT_D * IN_DIM * 2) : ka;
            CP16(sb + sm0,              Ahi + aOff0 + ka);
            CP16(sb + sm1,              Ahi + aOff1 + ka);
            CP16(sb + TILE_B + sm0,     Alo + aOff0 + ka);
            CP16(sb + TILE_B + sm1,     Alo + aOff1 + ka);
            CP16(sb + 2 * TILE_B + sm0, Bhi + bOff0 + kb);
            CP16(sb + 2 * TILE_B + sm1, Bhi + bOff1 + kb);
            CP16(sb + 3 * TILE_B + sm0, Blo + bOff0 + kb);
            CP16(sb + 3 * TILE_B + sm1, Blo + bOff1 + kb);
        }
        CP_COMMIT();
    };

    const int wm = (warp >> 2) * 64;
    const int wn = (warp & 3) * 32;
    const unsigned lrow  = lane & 15;
    const unsigned lcolB = (lane >> 4) * 16;

    float acc[4][4][4];
#pragma unroll
    for (int a = 0; a < 4; a++)
#pragma unroll
        for (int b = 0; b < 4; b++)
#pragma unroll
            for (int c = 0; c < 4; c++) acc[a][b][c] = 0.f;

    // Term-outer ordering: 16 independent accumulators between same-acc writes.
    auto COMPUTE = [&](int bi) {
        const unsigned base = sbase + bi * BUF_B;
#pragma unroll
        for (int ks = 0; ks < 2; ks++) {
            const unsigned kb = ks * 32 + lcolB;
            unsigned ahi[4][4], alo[4][4], bhi[2][4], blo[2][4];
#pragma unroll
            for (int mf = 0; mf < 4; mf++) {
                unsigned ad = base + (wm + mf * 16 + lrow) * ROWB + kb;
                ldsm_x4(ahi[mf], ad);
                ldsm_x4(alo[mf], ad + TILE_B);
            }
#pragma unroll
            for (int nf2 = 0; nf2 < 2; nf2++) {
                unsigned bd = base + 2 * TILE_B + (wn + nf2 * 16 + lrow) * ROWB + kb;
                ldsm_x4(bhi[nf2], bd);
                ldsm_x4(blo[nf2], bd + TILE_B);
            }
            // hi*hi sweep
#pragma unroll
            for (int mf = 0; mf < 4; mf++)
#pragma unroll
                for (int nf = 0; nf < 4; nf++) {
                    unsigned bh[2] = { bhi[nf >> 1][nf & 1], bhi[nf >> 1][(nf & 1) + 2] };
                    mma_bf16(acc[mf][nf], ahi[mf], bh);
                }
            // lo*hi sweep
#pragma unroll
            for (int mf = 0; mf < 4; mf++)
#pragma unroll
                for (int nf = 0; nf < 4; nf++) {
                    unsigned bh[2] = { bhi[nf >> 1][nf & 1], bhi[nf >> 1][(nf & 1) + 2] };
                    mma_bf16(acc[mf][nf], alo[mf], bh);
                }
            // hi*lo sweep
#pragma unroll
            for (int mf = 0; mf < 4; mf++)
#pragma unroll
                for (int nf = 0; nf < 4; nf++) {
                    unsigned bl[2] = { blo[nf >> 1][nf & 1], blo[nf >> 1][(nf & 1) + 2] };
                    mma_bf16(acc[mf][nf], ahi[mf], bl);
                }
        }
    };

    LOAD(0, 0); LOAD(1, 1);

    int bi = 0, li = 2;
    for (int s = 0; s < NKT; s++) {
        CP_WAIT1();
        __syncthreads();
        COMPUTE(bi);
        LOAD(s + 2, li);
        if (MODE == 2 && ((s & 31) == 31)) {
            const int h = s >> 5;
#pragma unroll
            for (int mf = 0; mf < 4; mf++)
#pragma unroll
                for (int eh = 0; eh < 2; eh++) {
                    const float sc = attnS[(wm + (lane >> 2) + mf * 16 + eh * 8) * NHEADS + h];
#pragma unroll
                    for (int nf = 0; nf < 4; nf++) {
#pragma unroll
                        for (int e = 0; e < 2; e++) {
                            const int idx = mf * 16 + nf * 4 + eh * 2 + e;
                            accT[idx * 256 + tid] += sc * acc[mf][nf][eh * 2 + e];
                            acc[mf][nf][eh * 2 + e] = 0.f;
                        }
                    }
                }
        }
        bi = (bi == 2) ? 0 : bi + 1;
        li = (li == 2) ? 0 : li + 1;
    }

    // ---- epilogue ----
    const int erow0 = wm + (lane >> 2);
    const int ecol0 = wn + (lane & 3) * 2;

    if (MODE == 0) {
#pragma unroll
        for (int mf = 0; mf < 4; mf++)
#pragma unroll
            for (int e2 = 0; e2 < 2; e2++) {
                int r = rowBase + erow0 + mf * 16 + e2 * 8;
#pragma unroll
                for (int nf = 0; nf < 4; nf++) {
                    int c = ecol0 + nf * 8;
                    float2 v;
                    v.x = acc[mf][nf][e2 * 2 + 0] + bias[c];
                    v.y = acc[mf][nf][e2 * 2 + 1] + bias[c + 1];
                    *(float2*)(out + (size_t)r * ATTN_D + c) = v;
                }
            }
    } else if (MODE == 1) {
#pragma unroll
        for (int mf = 0; mf < 4; mf++)
#pragma unroll
            for (int e2 = 0; e2 < 2; e2++) {
                int rl = erow0 + mf * 16 + e2 * 8;
                int rg = rowBase + rl;
                float s = 0.f;
#pragma unroll
                for (int nf = 0; nf < 4; nf++) {
                    int c = ecol0 + nf * 8;
                    float q0 = aux[(size_t)rg * ATTN_D + c];
                    float q1 = aux[(size_t)rg * ATTN_D + c + 1];
                    s += (acc[mf][nf][e2 * 2 + 0] + bias[bn * ATTN_D + c])     * q0;
                    s += (acc[mf][nf][e2 * 2 + 1] + bias[bn * ATTN_D + c + 1]) * q1;
                }
                atomicAdd(&sdot[rl], s);
            }
        __syncthreads();
        if (tid < 128)
            out[(size_t)(rowBase + tid) * NHEADS + bn] = sdot[tid];
    } else {
        // out = accT + sum_h attn[b,h]*bv[h,c]
#pragma unroll
        for (int nf = 0; nf < 4; nf++) {
            int c = bn * 128 + ecol0 + nf * 8;
            float bv0[NHEADS], bv1[NHEADS];
#pragma unroll
            for (int h = 0; h < NHEADS; h++) {
                bv0[h] = bias[h * OUT_D + c];
                bv1[h] = bias[h * OUT_D + c + 1];
            }
#pragma unroll
            for (int mf = 0; mf < 4; mf++)
#pragma unroll
                for (int e2 = 0; e2 < 2; e2++) {
                    int rl = erow0 + mf * 16 + e2 * 8;
                    int rg = rowBase + rl;
                    float b0 = 0.f, b1 = 0.f;
#pragma unroll
                    for (int h = 0; h < NHEADS; h++) {
                        float at = attnS[rl * NHEADS + h];
                        b0 += at * bv0[h];
                        b1 += at * bv1[h];
                    }
                    float2 v;
                    v.x = accT[(mf * 16 + nf * 4 + e2 * 2 + 0) * 256 + tid] + b0;
                    v.y = accT[(mf * 16 + nf * 4 + e2 * 2 + 1) * 256 + tid] + b1;
                    *(float2*)(out + (size_t)rg * OUT_D + c) = v;
                }
        }
    }
}

__global__ void softmax_kernel(const float* __restrict__ dot, float* __restrict__ attn) {
    int b = blockIdx.x * blockDim.x + threadIdx.x;
    if (b >= BATCH_N) return;
    const float sc = 0.08838834764831845f;
    float d[NHEADS], m = -1e30f;
#pragma unroll
    for (int h = 0; h < NHEADS; h++) { d[h] = dot[b * NHEADS + h] * sc; m = fmaxf(m, d[h]); }
    float s = 0.f;
#pragma unroll
    for (int h = 0; h < NHEADS; h++) { d[h] = __expf(d[h] - m); s += d[h]; }
    float inv = 1.f / s;
#pragma unroll
    for (int h = 0; h < NHEADS; h++) attn[b * NHEADS + h] = d[h] * inv;
}

extern "C" void kernel_launch(void* const* d_in, const int* in_sizes, int n_in,
                              void* d_out, int out_size) {
    const float* x  = (const float*)d_in[0];
    const float* Wq = (const float*)d_in[1];
    const float* bq = (const float*)d_in[2];
    const float* Wk = (const float*)d_in[3];
    const float* bk = (const float*)d_in[4];
    const float* Wv = (const float*)d_in[5];
    const float* bv = (const float*)d_in[6];
    float* out = (float*)d_out;

    float *qp, *dp, *ap;
    cudaGetSymbolAddress((void**)&qp, g_q);
    cudaGetSymbolAddress((void**)&dp, g_dot);
    cudaGetSymbolAddress((void**)&ap, g_attn);
    uint2 *xhi, *xlo, *wqhi, *wqlo, *wkhi, *wklo, *wvhi, *wvlo;
    cudaGetSymbolAddress((void**)&xhi,  g_xhi);
    cudaGetSymbolAddress((void**)&xlo,  g_xlo);
    cudaGetSymbolAddress((void**)&wqhi, g_wqhi);
    cudaGetSymbolAddress((void**)&wqlo, g_wqlo);
    cudaGetSymbolAddress((void**)&wkhi, g_wkhi);
    cudaGetSymbolAddress((void**)&wklo, g_wklo);
    cudaGetSymbolAddress((void**)&wvhi, g_wvhi);
    cudaGetSymbolAddress((void**)&wvlo, g_wvlo);

    cudaFuncSetAttribute(gemm_kernel<0, 32>,  cudaFuncAttributeMaxDynamicSharedMemorySize, SMEM_T01);
    cudaFuncSetAttribute(gemm_kernel<1, 32>,  cudaFuncAttributeMaxDynamicSharedMemorySize, SMEM_T01);
    cudaFuncSetAttribute(gemm_kernel<2, 256>, cudaFuncAttributeMaxDynamicSharedMemorySize, SMEM_T2);

    // pre-split fp32 -> bf16 hi/lo
    {
        int n4;
        n4 = BATCH_N * IN_DIM / 4;
        split_kernel<<<(n4 + 255) / 256, 256>>>((const float4*)x, xhi, xlo, n4);
        n4 = ATTN_D * IN_DIM / 4;
        split_kernel<<<(n4 + 255) / 256, 256>>>((const float4*)Wq, wqhi, wqlo, n4);
        n4 = NHEADS * ATTN_D * IN_DIM / 4;
        split_kernel<<<(n4 + 255) / 256, 256>>>((const float4*)Wk, wkhi, wklo, n4);
        n4 = (int)((size_t)NHEADS * OUT_D * IN_DIM / 4);
        split_kernel<<<(n4 + 255) / 256, 256>>>((const float4*)Wv, wvhi, wvlo, n4);
    }

    gemm_kernel<0, 32><<<dim3(BATCH_N / 128, 1), 256, SMEM_T01>>>(
        (const char*)xhi, (const char*)xlo, (const char*)wqhi, (const char*)wqlo, bq, nullptr, qp);
    gemm_kernel<1, 32><<<dim3(BATCH_N / 128, NHEADS), 256, SMEM_T01>>>(
        (const char*)xhi, (const char*)xlo, (const char*)wkhi, (const char*)wklo, bk, qp, dp);
    softmax_kernel<<<BATCH_N / 256, 256>>>(dp, ap);
    gemm_kernel<2, 256><<<dim3(BATCH_N / 128, NHEADS), 256, SMEM_T2>>>(
        (const char*)xhi, (const char*)xlo, (const char*)wvhi, (const char*)wvlo, bv, ap, out);
}

// round 13
// speedup vs baseline: 1.3232x; 1.3232x over previous
#include <cuda_runtime.h>
#include <cuda_bf16.h>
#include <cuda_fp16.h>
#include <math.h>
#include <stdint.h>

#define BATCH_N 32768
#define IN_DIM  1024
#define ATTN_D  128
#define OUT_D   1024
#define NHEADS  8

#define KT      32
#define PADE    40                 /* bf16/fp16 elems per smem row (32 data + 8 pad) */
#define ROWB    (PADE * 2)         /* 80 bytes per row */
#define TILE_B  (128 * ROWB)       /* 10240 bytes */
#define NSTAGE  4

// ---------------- device-global scratch (no cudaMalloc allowed) --------
__device__ float g_q[(size_t)BATCH_N * ATTN_D];
__device__ float g_dot[BATCH_N * NHEADS];
__device__ float g_attn[BATCH_N * NHEADS];
// bf16 hi/lo of x (Q/K gemms)
__device__ uint2 g_xhi[(size_t)BATCH_N * IN_DIM / 4];
__device__ uint2 g_xlo[(size_t)BATCH_N * IN_DIM / 4];
// fp16 hi/lo of x (V gemm)
__device__ uint2 g_xh16[(size_t)BATCH_N * IN_DIM / 4];
__device__ uint2 g_xl16[(size_t)BATCH_N * IN_DIM / 4];
// bf16 hi/lo weights for Q/K
__device__ uint2 g_wqhi[ATTN_D * IN_DIM / 4];
__device__ uint2 g_wqlo[ATTN_D * IN_DIM / 4];
__device__ uint2 g_wkhi[NHEADS * ATTN_D * IN_DIM / 4];
__device__ uint2 g_wklo[NHEADS * ATTN_D * IN_DIM / 4];
// fp16 hi of Wv (V gemm, 2-term split keeps only A residual)
__device__ uint2 g_wvh16[(size_t)NHEADS * OUT_D * IN_DIM / 4];

__device__ __forceinline__ unsigned smem_u32(const void* p) {
    return (unsigned)__cvta_generic_to_shared(p);
}

// fp32x4 -> (4 bf16 hi, 4 bf16 lo residual)
__device__ __forceinline__ void split4(float4 v, uint2& hi, uint2& lo) {
    __nv_bfloat162 h01 = __floats2bfloat162_rn(v.x, v.y);
    __nv_bfloat162 h23 = __floats2bfloat162_rn(v.z, v.w);
    float r0 = v.x - __bfloat162float(h01.x);
    float r1 = v.y - __bfloat162float(h01.y);
    float r2 = v.z - __bfloat162float(h23.x);
    float r3 = v.w - __bfloat162float(h23.y);
    __nv_bfloat162 l01 = __floats2bfloat162_rn(r0, r1);
    __nv_bfloat162 l23 = __floats2bfloat162_rn(r2, r3);
    hi.x = *(unsigned*)&h01; hi.y = *(unsigned*)&h23;
    lo.x = *(unsigned*)&l01; lo.y = *(unsigned*)&l23;
}
// fp32x4 -> (4 fp16 hi, 4 fp16 lo residual)
__device__ __forceinline__ void split4h(float4 v, uint2& hi, uint2& lo) {
    __half2 h01 = __floats2half2_rn(v.x, v.y);
    __half2 h23 = __floats2half2_rn(v.z, v.w);
    float r0 = v.x - __low2float(h01);
    float r1 = v.y - __high2float(h01);
    float r2 = v.z - __low2float(h23);
    float r3 = v.w - __high2float(h23);
    __half2 l01 = __floats2half2_rn(r0, r1);
    __half2 l23 = __floats2half2_rn(r2, r3);
    hi.x = *(unsigned*)&h01; hi.y = *(unsigned*)&h23;
    lo.x = *(unsigned*)&l01; lo.y = *(unsigned*)&l23;
}

// x: one pass producing bf16 hi/lo + fp16 hi/lo
__global__ void split_x_kernel(const float4* __restrict__ src,
                               uint2* __restrict__ bhi, uint2* __restrict__ blo,
                               uint2* __restrict__ fhi, uint2* __restrict__ flo, int n4) {
    int i = blockIdx.x * blockDim.x + threadIdx.x;
    if (i < n4) {
        float4 v = src[i];
        uint2 h, l;
        split4(v, h, l);  bhi[i] = h; blo[i] = l;
        split4h(v, h, l); fhi[i] = h; flo[i] = l;
    }
}
__global__ void split_kernel(const float4* __restrict__ src, uint2* __restrict__ hi,
                             uint2* __restrict__ lo, int n4) {
    int i = blockIdx.x * blockDim.x + threadIdx.x;
    if (i < n4) {
        uint2 h, l;
        split4(src[i], h, l);
        hi[i] = h; lo[i] = l;
    }
}
__global__ void conv_f16_kernel(const float4* __restrict__ src, uint2* __restrict__ hi, int n4) {
    int i = blockIdx.x * blockDim.x + threadIdx.x;
    if (i < n4) {
        float4 v = src[i];
        __half2 h01 = __floats2half2_rn(v.x, v.y);
        __half2 h23 = __floats2half2_rn(v.z, v.w);
        uint2 h; h.x = *(unsigned*)&h01; h.y = *(unsigned*)&h23;
        hi[i] = h;
    }
}

__device__ __forceinline__ void ldsm_x4(unsigned* r, unsigned addr) {
    asm volatile("ldmatrix.sync.aligned.m8n8.x4.shared.b16 {%0,%1,%2,%3}, [%4];"
                 : "=r"(r[0]), "=r"(r[1]), "=r"(r[2]), "=r"(r[3]) : "r"(addr));
}
__device__ __forceinline__ void mma_bf16(float* d, const unsigned* a, const unsigned* b) {
    asm volatile(
        "mma.sync.aligned.m16n8k16.row.col.f32.bf16.bf16.f32 "
        "{%0,%1,%2,%3}, {%4,%5,%6,%7}, {%8,%9}, {%0,%1,%2,%3};"
        : "+f"(d[0]), "+f"(d[1]), "+f"(d[2]), "+f"(d[3])
        : "r"(a[0]), "r"(a[1]), "r"(a[2]), "r"(a[3]), "r"(b[0]), "r"(b[1]));
}
__device__ __forceinline__ void mma_f16(float* d, const unsigned* a, const unsigned* b) {
    asm volatile(
        "mma.sync.aligned.m16n8k16.row.col.f32.f16.f16.f32 "
        "{%0,%1,%2,%3}, {%4,%5,%6,%7}, {%8,%9}, {%0,%1,%2,%3};"
        : "+f"(d[0]), "+f"(d[1]), "+f"(d[2]), "+f"(d[3])
        : "r"(a[0]), "r"(a[1]), "r"(a[2]), "r"(a[3]), "r"(b[0]), "r"(b[1]));
}

#define CP16(sm, gp) asm volatile("cp.async.cg.shared.global [%0], [%1], 16;" \
                                  :: "r"(sm), "l"(gp) : "memory")
#define CP_COMMIT()  asm volatile("cp.async.commit_group;" ::: "memory")
#define CP_WAIT2()   asm volatile("cp.async.wait_group 2;" ::: "memory")

// MODE 0: Q gemm (bf16x3)            out=g_q
// MODE 1: K gemm + q.k dot (bf16x3)  out=g_dot, aux=g_q
// MODE 2: V gemm (fp16x2, 2 tiles A + 1 tile B), per-head smem merge, out=d_out, aux=g_attn
template <int MODE, int NKT, int TERMS>
__global__ void __launch_bounds__(256, 1)
gemm_kernel(const char* __restrict__ Ahi, const char* __restrict__ Alo,
            const char* __restrict__ Bhi, const char* __restrict__ Blo,
            const float* __restrict__ bias, const float* __restrict__ aux,
            float* __restrict__ out) {
    constexpr int NTILES = (TERMS == 3) ? 4 : 3;
    constexpr int BUFB   = NTILES * TILE_B;
    constexpr int AOFF   = NSTAGE * BUFB;           // attnS / sdot
    constexpr int TOFF   = AOFF + 4096;             // accT (MODE 2)

    extern __shared__ char smem[];
    const unsigned sbase = smem_u32(smem);
    const int tid  = threadIdx.x;
    const int warp = tid >> 5, lane = tid & 31;
    const int bm = blockIdx.x;
    const int bn = blockIdx.y;
    const int rowBase = bm * 128;
    const int bRowBase = (MODE == 0) ? 0 : bn * 128;

    float* attnS = (float*)(smem + AOFF);
    float* sdot  = (float*)(smem + AOFF);
    float* accT  = (float*)(smem + TOFF);           // [64][256]

    if (MODE == 1) { if (tid < 128) sdot[tid] = 0.f; }
    if (MODE == 2) {
        for (int i = tid; i < 128 * NHEADS; i += 256)
            attnS[i] = aux[(size_t)(rowBase + (i >> 3)) * NHEADS + (i & 7)];
#pragma unroll
        for (int i = 0; i < 64; i++) accT[i * 256 + tid] = 0.f;
    }

    // per-thread copy slots: 2 chunks of 16B per tile
    const int row0 = tid >> 2,          c0 = tid & 3;
    const int row1 = (tid + 256) >> 2,  c1 = (tid + 256) & 3;
    const size_t aOff0 = ((size_t)(rowBase + row0) * IN_DIM + c0 * 8) * 2;
    const size_t aOff1 = ((size_t)(rowBase + row1) * IN_DIM + c1 * 8) * 2;
    const size_t bOff0 = ((size_t)(bRowBase + row0) * IN_DIM + c0 * 8) * 2;
    const size_t bOff1 = ((size_t)(bRowBase + row1) * IN_DIM + c1 * 8) * 2;
    const unsigned sm0 = row0 * ROWB + c0 * 16;
    const unsigned sm1 = row1 * ROWB + c1 * 16;

    auto LOAD = [&](int s) {
        if (s < NKT) {
            const unsigned sb = sbase + (s & 3) * BUFB;
            const size_t ka = (size_t)((s * KT) & (IN_DIM - 1)) * 2;
            const size_t kb = (MODE == 2)
                ? ka + (size_t)(s >> 5) * ((size_t)OUT_D * IN_DIM * 2) : ka;
            CP16(sb + sm0,              Ahi + aOff0 + ka);
            CP16(sb + sm1,              Ahi + aOff1 + ka);
            CP16(sb + TILE_B + sm0,     Alo + aOff0 + ka);
            CP16(sb + TILE_B + sm1,     Alo + aOff1 + ka);
            CP16(sb + 2 * TILE_B + sm0, Bhi + bOff0 + kb);
            CP16(sb + 2 * TILE_B + sm1, Bhi + bOff1 + kb);
            if (TERMS == 3) {
                CP16(sb + 3 * TILE_B + sm0, Blo + bOff0 + kb);
                CP16(sb + 3 * TILE_B + sm1, Blo + bOff1 + kb);
            }
        }
        CP_COMMIT();
    };

    const int wm = (warp >> 2) * 64;
    const int wn = (warp & 3) * 32;
    const unsigned lrow  = lane & 15;
    const unsigned lcolB = (lane >> 4) * 16;

    float acc[4][4][4];
#pragma unroll
    for (int a = 0; a < 4; a++)
#pragma unroll
        for (int b = 0; b < 4; b++)
#pragma unroll
            for (int c = 0; c < 4; c++) acc[a][b][c] = 0.f;

    auto COMPUTE = [&](int t) {
        const unsigned base = sbase + (t & 3) * BUFB;
#pragma unroll
        for (int ks = 0; ks < 2; ks++) {
            const unsigned kb = ks * 32 + lcolB;
            unsigned ahi[4][4], alo[4][4], bhi[2][4];
#pragma unroll
            for (int mf = 0; mf < 4; mf++) {
                unsigned ad = base + (wm + mf * 16 + lrow) * ROWB + kb;
                ldsm_x4(ahi[mf], ad);
                ldsm_x4(alo[mf], ad + TILE_B);
            }
#pragma unroll
            for (int nf2 = 0; nf2 < 2; nf2++) {
                unsigned bd = base + 2 * TILE_B + (wn + nf2 * 16 + lrow) * ROWB + kb;
                ldsm_x4(bhi[nf2], bd);
            }
            if (TERMS == 2) {
                // fp16x2: hi*hi sweep then lo*hi sweep (16 indep accs between writes)
#pragma unroll
                for (int mf = 0; mf < 4; mf++)
#pragma unroll
                    for (int nf = 0; nf < 4; nf++) {
                        unsigned bh[2] = { bhi[nf >> 1][nf & 1], bhi[nf >> 1][(nf & 1) + 2] };
                        mma_f16(acc[mf][nf], ahi[mf], bh);
                    }
#pragma unroll
                for (int mf = 0; mf < 4; mf++)
#pragma unroll
                    for (int nf = 0; nf < 4; nf++) {
                        unsigned bh[2] = { bhi[nf >> 1][nf & 1], bhi[nf >> 1][(nf & 1) + 2] };
                        mma_f16(acc[mf][nf], alo[mf], bh);
                    }
            } else {
                unsigned blo[2][4];
#pragma unroll
                for (int nf2 = 0; nf2 < 2; nf2++) {
                    unsigned bd = base + 3 * TILE_B + (wn + nf2 * 16 + lrow) * ROWB + kb;
                    ldsm_x4(blo[nf2], bd);
                }
#pragma unroll
                for (int mf = 0; mf < 4; mf++)
#pragma unroll
                    for (int nf = 0; nf < 4; nf++) {
                        unsigned bh[2] = { bhi[nf >> 1][nf & 1], bhi[nf >> 1][(nf & 1) + 2] };
                        unsigned bl[2] = { blo[nf >> 1][nf & 1], blo[nf >> 1][(nf & 1) + 2] };
                        mma_bf16(acc[mf][nf], ahi[mf], bh);
                        mma_bf16(acc[mf][nf], alo[mf], bh);
                        mma_bf16(acc[mf][nf], ahi[mf], bl);
                    }
            }
        }
    };

    LOAD(0); LOAD(1); LOAD(2);

    for (int s = 0; s < NKT; s++) {
        CP_WAIT2();
        __syncthreads();
        COMPUTE(s);
        if (MODE == 2 && ((s & 31) == 31)) {
            const int h = s >> 5;
#pragma unroll
            for (int mf = 0; mf < 4; mf++)
#pragma unroll
                for (int eh = 0; eh < 2; eh++) {
                    const float sc = attnS[(wm + (lane >> 2) + mf * 16 + eh * 8) * NHEADS + h];
#pragma unroll
                    for (int nf = 0; nf < 4; nf++)
#pragma unroll
                        for (int e = 0; e < 2; e++) {
                            const int idx = mf * 16 + nf * 4 + eh * 2 + e;
                            accT[idx * 256 + tid] += sc * acc[mf][nf][eh * 2 + e];
                            acc[mf][nf][eh * 2 + e] = 0.f;
                        }
                }
        }
        LOAD(s + 3);
    }

    // ---- epilogue ----
    const int erow0 = wm + (lane >> 2);
    const int ecol0 = wn + (lane & 3) * 2;

    if (MODE == 0) {
#pragma unroll
        for (int mf = 0; mf < 4; mf++)
#pragma unroll
            for (int e2 = 0; e2 < 2; e2++) {
                int r = rowBase + erow0 + mf * 16 + e2 * 8;
#pragma unroll
                for (int nf = 0; nf < 4; nf++) {
                    int c = ecol0 + nf * 8;
                    float2 v;
                    v.x = acc[mf][nf][e2 * 2 + 0] + bias[c];
                    v.y = acc[mf][nf][e2 * 2 + 1] + bias[c + 1];
                    *(float2*)(out + (size_t)r * ATTN_D + c) = v;
                }
            }
    } else if (MODE == 1) {
#pragma unroll
        for (int mf = 0; mf < 4; mf++)
#pragma unroll
            for (int e2 = 0; e2 < 2; e2++) {
                int rl = erow0 + mf * 16 + e2 * 8;
                int rg = rowBase + rl;
                float s = 0.f;
#pragma unroll
                for (int nf = 0; nf < 4; nf++) {
                    int c = ecol0 + nf * 8;
                    float q0 = aux[(size_t)rg * ATTN_D + c];
                    float q1 = aux[(size_t)rg * ATTN_D + c + 1];
                    s += (acc[mf][nf][e2 * 2 + 0] + bias[bn * ATTN_D + c])     * q0;
                    s += (acc[mf][nf][e2 * 2 + 1] + bias[bn * ATTN_D + c + 1]) * q1;
                }
                atomicAdd(&sdot[rl], s);
            }
        __syncthreads();
        if (tid < 128)
            out[(size_t)(rowBase + tid) * NHEADS + bn] = sdot[tid];
    } else {
#pragma unroll
        for (int nf = 0; nf < 4; nf++) {
            int c = bn * 128 + ecol0 + nf * 8;
            float bv0[NHEADS], bv1[NHEADS];
#pragma unroll
            for (int h = 0; h < NHEADS; h++) {
                bv0[h] = bias[h * OUT_D + c];
                bv1[h] = bias[h * OUT_D + c + 1];
            }
#pragma unroll
            for (int mf = 0; mf < 4; mf++)
#pragma unroll
                for (int e2 = 0; e2 < 2; e2++) {
                    int rl = erow0 + mf * 16 + e2 * 8;
                    int rg = rowBase + rl;
                    float b0 = 0.f, b1 = 0.f;
#pragma unroll
                    for (int h = 0; h < NHEADS; h++) {
                        float at = attnS[rl * NHEADS + h];
                        b0 += at * bv0[h];
                        b1 += at * bv1[h];
                    }
                    float2 v;
                    v.x = accT[(mf * 16 + nf * 4 + e2 * 2 + 0) * 256 + tid] + b0;
                    v.y = accT[(mf * 16 + nf * 4 + e2 * 2 + 1) * 256 + tid] + b1;
                    *(float2*)(out + (size_t)rg * OUT_D + c) = v;
                }
        }
    }
}

__global__ void softmax_kernel(const float* __restrict__ dot, float* __restrict__ attn) {
    int b = blockIdx.x * blockDim.x + threadIdx.x;
    if (b >= BATCH_N) return;
    const float sc = 0.08838834764831845f;
    float d[NHEADS], m = -1e30f;
#pragma unroll
    for (int h = 0; h < NHEADS; h++) { d[h] = dot[b * NHEADS + h] * sc; m = fmaxf(m, d[h]); }
    float s = 0.f;
#pragma unroll
    for (int h = 0; h < NHEADS; h++) { d[h] = __expf(d[h] - m); s += d[h]; }
    float inv = 1.f / s;
#pragma unroll
    for (int h = 0; h < NHEADS; h++) attn[b * NHEADS + h] = d[h] * inv;
}

extern "C" void kernel_launch(void* const* d_in, const int* in_sizes, int n_in,
                              void* d_out, int out_size) {
    const float* x  = (const float*)d_in[0];
    const float* Wq = (const float*)d_in[1];
    const float* bq = (const float*)d_in[2];
    const float* Wk = (const float*)d_in[3];
    const float* bk = (const float*)d_in[4];
    const float* Wv = (const float*)d_in[5];
    const float* bv = (const float*)d_in[6];
    float* out = (float*)d_out;

    float *qp, *dp, *ap;
    cudaGetSymbolAddress((void**)&qp, g_q);
    cudaGetSymbolAddress((void**)&dp, g_dot);
    cudaGetSymbolAddress((void**)&ap, g_attn);
    uint2 *xhi, *xlo, *xh16, *xl16, *wqhi, *wqlo, *wkhi, *wklo, *wvh16;
    cudaGetSymbolAddress((void**)&xhi,   g_xhi);
    cudaGetSymbolAddress((void**)&xlo,   g_xlo);
    cudaGetSymbolAddress((void**)&xh16,  g_xh16);
    cudaGetSymbolAddress((void**)&xl16,  g_xl16);
    cudaGetSymbolAddress((void**)&wqhi,  g_wqhi);
    cudaGetSymbolAddress((void**)&wqlo,  g_wqlo);
    cudaGetSymbolAddress((void**)&wkhi,  g_wkhi);
    cudaGetSymbolAddress((void**)&wklo,  g_wklo);
    cudaGetSymbolAddress((void**)&wvh16, g_wvh16);

    constexpr int SMEM_T01 = NSTAGE * 4 * TILE_B + 4096;            // 167936
    constexpr int SMEM_T2  = NSTAGE * 3 * TILE_B + 4096 + 65536;    // 192512
    cudaFuncSetAttribute(gemm_kernel<0, 32, 3>,  cudaFuncAttributeMaxDynamicSharedMemorySize, SMEM_T01);
    cudaFuncSetAttribute(gemm_kernel<1, 32, 3>,  cudaFuncAttributeMaxDynamicSharedMemorySize, SMEM_T01);
    cudaFuncSetAttribute(gemm_kernel<2, 256, 2>, cudaFuncAttributeMaxDynamicSharedMemorySize, SMEM_T2);

    // pre-pass: splits / conversions
    {
        int n4;
        n4 = BATCH_N * IN_DIM / 4;
        split_x_kernel<<<(n4 + 255) / 256, 256>>>((const float4*)x, xhi, xlo, xh16, xl16, n4);
        n4 = ATTN_D * IN_DIM / 4;
        split_kernel<<<(n4 + 255) / 256, 256>>>((const float4*)Wq, wqhi, wqlo, n4);
        n4 = NHEADS * ATTN_D * IN_DIM / 4;
        split_kernel<<<(n4 + 255) / 256, 256>>>((const float4*)Wk, wkhi, wklo, n4);
        n4 = (int)((size_t)NHEADS * OUT_D * IN_DIM / 4);
        conv_f16_kernel<<<(n4 + 255) / 256, 256>>>((const float4*)Wv, wvh16, n4);
    }

    gemm_kernel<0, 32, 3><<<dim3(BATCH_N / 128, 1), 256, SMEM_T01>>>(
        (const char*)xhi, (const char*)xlo, (const char*)wqhi, (const char*)wqlo, bq, nullptr, qp);
    gemm_kernel<1, 32, 3><<<dim3(BATCH_N / 128, NHEADS), 256, SMEM_T01>>>(
        (const char*)xhi, (const char*)xlo, (const char*)wkhi, (const char*)wklo, bk, qp, dp);
    softmax_kernel<<<BATCH_N / 256, 256>>>(dp, ap);
    gemm_kernel<2, 256, 2><<<dim3(BATCH_N / 128, NHEADS), 256, SMEM_T2>>>(
        (const char*)xh16, (const char*)xl16, (const char*)wvh16, nullptr, bv, ap, out);
}

// round 15
// speedup vs baseline: 2.4687x; 1.8658x over previous
#include <cuda_runtime.h>
#include <cuda_fp16.h>
#include <math.h>
#include <stdint.h>

#define BATCH_N 32768
#define IN_DIM  1024
#define ATTN_D  128
#define OUT_D   1024
#define NHEADS  8

#define KT      32
#define PADE    40                 /* fp16 elems per smem row (32 data + 8 pad) */
#define ROWB    (PADE * 2)         /* 80 bytes per row */
#define TILE_B  (128 * ROWB)       /* 10240 bytes */
#define NSTAGE  4
#define BUFB    (2 * TILE_B)       /* A hi + B hi = 20480 */
#define AOFF    (NSTAGE * BUFB)    /* 81920: attnS / sdot */
#define TOFF    (AOFF + 4096)      /* accT (MODE 2) */
#define SMEM_T01 (AOFF + 4096)               /* 86016 */
#define SMEM_T2  (TOFF + 65536)              /* 151552 */

// ---------------- device-global scratch (no cudaMalloc allowed) --------
__device__ float g_q[(size_t)BATCH_N * ATTN_D];
__device__ float g_dot[BATCH_N * NHEADS];
__device__ float g_attn[BATCH_N * NHEADS];
__device__ uint2 g_x16[(size_t)BATCH_N * IN_DIM / 4];
__device__ uint2 g_wq16[ATTN_D * IN_DIM / 4];
__device__ uint2 g_wk16[NHEADS * ATTN_D * IN_DIM / 4];
__device__ uint2 g_wv16[(size_t)NHEADS * OUT_D * IN_DIM / 4];

__device__ __forceinline__ unsigned smem_u32(const void* p) {
    return (unsigned)__cvta_generic_to_shared(p);
}

__global__ void conv_f16_kernel(const float4* __restrict__ src, uint2* __restrict__ dst, int n4) {
    int i = blockIdx.x * blockDim.x + threadIdx.x;
    if (i < n4) {
        float4 v = src[i];
        __half2 h01 = __floats2half2_rn(v.x, v.y);
        __half2 h23 = __floats2half2_rn(v.z, v.w);
        uint2 h; h.x = *(unsigned*)&h01; h.y = *(unsigned*)&h23;
        dst[i] = h;
    }
}

__device__ __forceinline__ void ldsm_x4(unsigned* r, unsigned addr) {
    asm volatile("ldmatrix.sync.aligned.m8n8.x4.shared.b16 {%0,%1,%2,%3}, [%4];"
                 : "=r"(r[0]), "=r"(r[1]), "=r"(r[2]), "=r"(r[3]) : "r"(addr));
}
__device__ __forceinline__ void mma_f16(float* d, const unsigned* a, const unsigned* b) {
    asm volatile(
        "mma.sync.aligned.m16n8k16.row.col.f32.f16.f16.f32 "
        "{%0,%1,%2,%3}, {%4,%5,%6,%7}, {%8,%9}, {%0,%1,%2,%3};"
        : "+f"(d[0]), "+f"(d[1]), "+f"(d[2]), "+f"(d[3])
        : "r"(a[0]), "r"(a[1]), "r"(a[2]), "r"(a[3]), "r"(b[0]), "r"(b[1]));
}

#define CP16(sm, gp) asm volatile("cp.async.cg.shared.global [%0], [%1], 16;" \
                                  :: "r"(sm), "l"(gp) : "memory")
#define CP_COMMIT()  asm volatile("cp.async.commit_group;" ::: "memory")
#define CP_WAIT2()   asm volatile("cp.async.wait_group 2;" ::: "memory")

// MODE 0: Q gemm (N=128)             out=g_q
// MODE 1: K gemm + q.k dot epilogue  out=g_dot, aux=g_q
// MODE 2: V gemm, per-head smem merge out=d_out, aux=g_attn  (NKT=256)
template <int MODE, int NKT>
__global__ void __launch_bounds__(256, 1)
gemm_kernel(const char* __restrict__ A16, const char* __restrict__ B16,
            const float* __restrict__ bias, const float* __restrict__ aux,
            float* __restrict__ out) {
    extern __shared__ char smem[];
    const unsigned sbase = smem_u32(smem);
    const int tid  = threadIdx.x;
    const int warp = tid >> 5, lane = tid & 31;
    const int bm = blockIdx.x;
    const int bn = blockIdx.y;
    const int rowBase = bm * 128;
    const int bRowBase = (MODE == 0) ? 0 : bn * 128;

    float* attnS = (float*)(smem + AOFF);
    float* sdot  = (float*)(smem + AOFF);
    float* accT  = (float*)(smem + TOFF);           // MODE 2: [64][256]

    if (MODE == 1) { if (tid < 128) sdot[tid] = 0.f; }
    if (MODE == 2) {
        for (int i = tid; i < 128 * NHEADS; i += 256)
            attnS[i] = aux[(size_t)(rowBase + (i >> 3)) * NHEADS + (i & 7)];
#pragma unroll
        for (int i = 0; i < 64; i++) accT[i * 256 + tid] = 0.f;
    }

    // per-thread copy slots: 2 chunks of 16B per tile (rows 0-63, 64-127)
    const int row0 = tid >> 2,          c0 = tid & 3;
    const int row1 = (tid + 256) >> 2,  c1 = (tid + 256) & 3;
    const size_t aOff0 = ((size_t)(rowBase + row0) * IN_DIM + c0 * 8) * 2;
    const size_t aOff1 = ((size_t)(rowBase + row1) * IN_DIM + c1 * 8) * 2;
    const size_t bOff0 = ((size_t)(bRowBase + row0) * IN_DIM + c0 * 8) * 2;
    const size_t bOff1 = ((size_t)(bRowBase + row1) * IN_DIM + c1 * 8) * 2;
    const unsigned sm0 = row0 * ROWB + c0 * 16;
    const unsigned sm1 = row1 * ROWB + c1 * 16;

    auto LOAD = [&](int s) {
        if (s < NKT) {
            const unsigned sb = sbase + (s & 3) * BUFB;
            const size_t ka = (size_t)((s * KT) & (IN_DIM - 1)) * 2;
            const size_t kb = (MODE == 2)
                ? ka + (size_t)(s >> 5) * ((size_t)OUT_D * IN_DIM * 2) : ka;
            CP16(sb + sm0,          A16 + aOff0 + ka);
            CP16(sb + sm1,          A16 + aOff1 + ka);
            CP16(sb + TILE_B + sm0, B16 + bOff0 + kb);
            CP16(sb + TILE_B + sm1, B16 + bOff1 + kb);
        }
        CP_COMMIT();
    };

    const int wm = (warp >> 2) * 64;
    const int wn = (warp & 3) * 32;
    const unsigned lrow  = lane & 15;
    const unsigned lcolB = (lane >> 4) * 16;

    float acc[4][4][4];
#pragma unroll
    for (int a = 0; a < 4; a++)
#pragma unroll
        for (int b = 0; b < 4; b++)
#pragma unroll
            for (int c = 0; c < 4; c++) acc[a][b][c] = 0.f;

    auto COMPUTE = [&](int t) {
        const unsigned base = sbase + (t & 3) * BUFB;
#pragma unroll
        for (int ks = 0; ks < 2; ks++) {
            const unsigned kb = ks * 32 + lcolB;
            unsigned af[4][4], bf[2][4];
#pragma unroll
            for (int mf = 0; mf < 4; mf++) {
                unsigned ad = base + (wm + mf * 16 + lrow) * ROWB + kb;
                ldsm_x4(af[mf], ad);
            }
#pragma unroll
            for (int nf2 = 0; nf2 < 2; nf2++) {
                unsigned bd = base + TILE_B + (wn + nf2 * 16 + lrow) * ROWB + kb;
                ldsm_x4(bf[nf2], bd);
            }
#pragma unroll
            for (int mf = 0; mf < 4; mf++)
#pragma unroll
                for (int nf = 0; nf < 4; nf++) {
                    unsigned bh[2] = { bf[nf >> 1][nf & 1], bf[nf >> 1][(nf & 1) + 2] };
                    mma_f16(acc[mf][nf], af[mf], bh);
                }
        }
    };

    LOAD(0); LOAD(1); LOAD(2);

    for (int s = 0; s < NKT; s++) {
        CP_WAIT2();
        __syncthreads();
        COMPUTE(s);
        if (MODE == 2 && ((s & 31) == 31)) {
            const int h = s >> 5;
#pragma unroll
            for (int mf = 0; mf < 4; mf++)
#pragma unroll
                for (int eh = 0; eh < 2; eh++) {
                    const float sc = attnS[(wm + (lane >> 2) + mf * 16 + eh * 8) * NHEADS + h];
#pragma unroll
                    for (int nf = 0; nf < 4; nf++)
#pragma unroll
                        for (int e = 0; e < 2; e++) {
                            const int idx = mf * 16 + nf * 4 + eh * 2 + e;
                            accT[idx * 256 + tid] += sc * acc[mf][nf][eh * 2 + e];
                            acc[mf][nf][eh * 2 + e] = 0.f;
                        }
                }
        }
        LOAD(s + 3);
    }

    // ---- epilogue ----
    const int erow0 = wm + (lane >> 2);
    const int ecol0 = wn + (lane & 3) * 2;

    if (MODE == 0) {
#pragma unroll
        for (int mf = 0; mf < 4; mf++)
#pragma unroll
            for (int e2 = 0; e2 < 2; e2++) {
                int r = rowBase + erow0 + mf * 16 + e2 * 8;
#pragma unroll
                for (int nf = 0; nf < 4; nf++) {
                    int c = ecol0 + nf * 8;
                    float2 v;
                    v.x = acc[mf][nf][e2 * 2 + 0] + bias[c];
                    v.y = acc[mf][nf][e2 * 2 + 1] + bias[c + 1];
                    *(float2*)(out + (size_t)r * ATTN_D + c) = v;
                }
            }
    } else if (MODE == 1) {
#pragma unroll
        for (int mf = 0; mf < 4; mf++)
#pragma unroll
            for (int e2 = 0; e2 < 2; e2++) {
                int rl = erow0 + mf * 16 + e2 * 8;
                int rg = rowBase + rl;
                float s = 0.f;
#pragma unroll
                for (int nf = 0; nf < 4; nf++) {
                    int c = ecol0 + nf * 8;
                    float q0 = aux[(size_t)rg * ATTN_D + c];
                    float q1 = aux[(size_t)rg * ATTN_D + c + 1];
                    s += (acc[mf][nf][e2 * 2 + 0] + bias[bn * ATTN_D + c])     * q0;
                    s += (acc[mf][nf][e2 * 2 + 1] + bias[bn * ATTN_D + c + 1]) * q1;
                }
                atomicAdd(&sdot[rl], s);
            }
        __syncthreads();
        if (tid < 128)
            out[(size_t)(rowBase + tid) * NHEADS + bn] = sdot[tid];
    } else {
#pragma unroll
        for (int nf = 0; nf < 4; nf++) {
            int c = bn * 128 + ecol0 + nf * 8;
            float bv0[NHEADS], bv1[NHEADS];
#pragma unroll
            for (int h = 0; h < NHEADS; h++) {
                bv0[h] = bias[h * OUT_D + c];
                bv1[h] = bias[h * OUT_D + c + 1];
            }
#pragma unroll
            for (int mf = 0; mf < 4; mf++)
#pragma unroll
                for (int e2 = 0; e2 < 2; e2++) {
                    int rl = erow0 + mf * 16 + e2 * 8;
                    int rg = rowBase + rl;
                    float b0 = 0.f, b1 = 0.f;
#pragma unroll
                    for (int h = 0; h < NHEADS; h++) {
                        float at = attnS[rl * NHEADS + h];
                        b0 += at * bv0[h];
                        b1 += at * bv1[h];
                    }
                    float2 v;
                    v.x = accT[(mf * 16 + nf * 4 + e2 * 2 + 0) * 256 + tid] + b0;
                    v.y = accT[(mf * 16 + nf * 4 + e2 * 2 + 1) * 256 + tid] + b1;
                    *(float2*)(out + (size_t)rg * OUT_D + c) = v;
                }
        }
    }
}

__global__ void softmax_kernel(const float* __restrict__ dot, float* __restrict__ attn) {
    int b = blockIdx.x * blockDim.x + threadIdx.x;
    if (b >= BATCH_N) return;
    const float sc = 0.08838834764831845f;
    float d[NHEADS], m = -1e30f;
#pragma unroll
    for (int h = 0; h < NHEADS; h++) { d[h] = dot[b * NHEADS + h] * sc; m = fmaxf(m, d[h]); }
    float s = 0.f;
#pragma unroll
    for (int h = 0; h < NHEADS; h++) { d[h] = __expf(d[h] - m); s += d[h]; }
    float inv = 1.f / s;
#pragma unroll
    for (int h = 0; h < NHEADS; h++) attn[b * NHEADS + h] = d[h] * inv;
}

extern "C" void kernel_launch(void* const* d_in, const int* in_sizes, int n_in,
                              void* d_out, int out_size) {
    const float* x  = (const float*)d_in[0];
    const float* Wq = (const float*)d_in[1];
    const float* bq = (const float*)d_in[2];
    const float* Wk = (const float*)d_in[3];
    const float* bk = (const float*)d_in[4];
    const float* Wv = (const float*)d_in[5];
    const float* bv = (const float*)d_in[6];
    float* out = (float*)d_out;

    float *qp, *dp, *ap;
    cudaGetSymbolAddress((void**)&qp, g_q);
    cudaGetSymbolAddress((void**)&dp, g_dot);
    cudaGetSymbolAddress((void**)&ap, g_attn);
    uint2 *x16, *wq16, *wk16, *wv16;
    cudaGetSymbolAddress((void**)&x16,  g_x16);
    cudaGetSymbolAddress((void**)&wq16, g_wq16);
    cudaGetSymbolAddress((void**)&wk16, g_wk16);
    cudaGetSymbolAddress((void**)&wv16, g_wv16);

    cudaFuncSetAttribute(gemm_kernel<0, 32>,  cudaFuncAttributeMaxDynamicSharedMemorySize, SMEM_T01);
    cudaFuncSetAttribute(gemm_kernel<1, 32>,  cudaFuncAttributeMaxDynamicSharedMemorySize, SMEM_T01);
    cudaFuncSetAttribute(gemm_kernel<2, 256>, cudaFuncAttributeMaxDynamicSharedMemorySize, SMEM_T2);

    // pre-pass: fp32 -> fp16 conversions
    {
        int n4;
        n4 = BATCH_N * IN_DIM / 4;
        conv_f16_kernel<<<(n4 + 255) / 256, 256>>>((const float4*)x, x16, n4);
        n4 = ATTN_D * IN_DIM / 4;
        conv_f16_kernel<<<(n4 + 255) / 256, 256>>>((const float4*)Wq, wq16, n4);
        n4 = NHEADS * ATTN_D * IN_DIM / 4;
        conv_f16_kernel<<<(n4 + 255) / 256, 256>>>((const float4*)Wk, wk16, n4);
        n4 = (int)((size_t)NHEADS * OUT_D * IN_DIM / 4);
        conv_f16_kernel<<<(n4 + 255) / 256, 256>>>((const float4*)Wv, wv16, n4);
    }

    gemm_kernel<0, 32><<<dim3(BATCH_N / 128, 1), 256, SMEM_T01>>>(
        (const char*)x16, (const char*)wq16, bq, nullptr, qp);
    gemm_kernel<1, 32><<<dim3(BATCH_N / 128, NHEADS), 256, SMEM_T01>>>(
        (const char*)x16, (const char*)wk16, bk, qp, dp);
    softmax_kernel<<<BATCH_N / 256, 256>>>(dp, ap);
    gemm_kernel<2, 256><<<dim3(BATCH_N / 128, NHEADS), 256, SMEM_T2>>>(
        (const char*)x16, (const char*)wv16, bv, ap, out);
}

// round 16
// speedup vs baseline: 2.8539x; 1.1560x over previous
#include <cuda_runtime.h>
#include <cuda_fp16.h>
#include <math.h>
#include <stdint.h>

#define BATCH_N 32768
#define IN_DIM  1024
#define ATTN_D  128
#define OUT_D   1024
#define NHEADS  8

#define KT      64
#define PADE    72                 /* fp16 elems per smem row (64 data + 8 pad) */
#define ROWB    (PADE * 2)         /* 144 bytes per row */
#define TILE_B  (128 * ROWB)       /* 18432 bytes */
#define NSTAGE  3
#define BUFB    (2 * TILE_B)       /* A + B = 36864 */
#define AOFF    (NSTAGE * BUFB)    /* 110592: attnS / sdot */
#define TOFF    (AOFF + 4096)      /* accT (MODE 2) */
#define SMEM_T01 (AOFF + 4096)     /* 114688 */
#define SMEM_T2  (TOFF + 65536)    /* 180224 */

// ---------------- device-global scratch (no cudaMalloc allowed) --------
__device__ float g_q[(size_t)BATCH_N * ATTN_D];
__device__ float g_dot[BATCH_N * NHEADS];
__device__ float g_attn[BATCH_N * NHEADS];
__device__ uint2 g_x16[(size_t)BATCH_N * IN_DIM / 4];
__device__ uint2 g_wq16[ATTN_D * IN_DIM / 4];
__device__ uint2 g_wk16[NHEADS * ATTN_D * IN_DIM / 4];
__device__ uint2 g_wv16[(size_t)NHEADS * OUT_D * IN_DIM / 4];

__device__ __forceinline__ unsigned smem_u32(const void* p) {
    return (unsigned)__cvta_generic_to_shared(p);
}

__global__ void conv_f16_kernel(const float4* __restrict__ src, uint2* __restrict__ dst, int n4) {
    int i = blockIdx.x * blockDim.x + threadIdx.x;
    if (i < n4) {
        float4 v = src[i];
        __half2 h01 = __floats2half2_rn(v.x, v.y);
        __half2 h23 = __floats2half2_rn(v.z, v.w);
        uint2 h; h.x = *(unsigned*)&h01; h.y = *(unsigned*)&h23;
        dst[i] = h;
    }
}

__device__ __forceinline__ void ldsm_x4(unsigned* r, unsigned addr) {
    asm volatile("ldmatrix.sync.aligned.m8n8.x4.shared.b16 {%0,%1,%2,%3}, [%4];"
                 : "=r"(r[0]), "=r"(r[1]), "=r"(r[2]), "=r"(r[3]) : "r"(addr));
}
__device__ __forceinline__ void mma_f16(float* d, const unsigned* a, const unsigned* b) {
    asm volatile(
        "mma.sync.aligned.m16n8k16.row.col.f32.f16.f16.f32 "
        "{%0,%1,%2,%3}, {%4,%5,%6,%7}, {%8,%9}, {%0,%1,%2,%3};"
        : "+f"(d[0]), "+f"(d[1]), "+f"(d[2]), "+f"(d[3])
        : "r"(a[0]), "r"(a[1]), "r"(a[2]), "r"(a[3]), "r"(b[0]), "r"(b[1]));
}

#define CP16(sm, gp) asm volatile("cp.async.cg.shared.global [%0], [%1], 16;" \
                                  :: "r"(sm), "l"(gp) : "memory")
#define CP_COMMIT()  asm volatile("cp.async.commit_group;" ::: "memory")
#define CP_WAIT1()   asm volatile("cp.async.wait_group 1;" ::: "memory")

// MODE 0: Q gemm (N=128)             out=g_q
// MODE 1: K gemm + q.k dot epilogue  out=g_dot, aux=g_q
// MODE 2: V gemm, per-head smem merge out=d_out, aux=g_attn  (NKT=128)
template <int MODE, int NKT>
__global__ void __launch_bounds__(256, 1)
gemm_kernel(const char* __restrict__ A16, const char* __restrict__ B16,
            const float* __restrict__ bias, const float* __restrict__ aux,
            float* __restrict__ out) {
    extern __shared__ char smem[];
    const unsigned sbase = smem_u32(smem);
    const int tid  = threadIdx.x;
    const int warp = tid >> 5, lane = tid & 31;
    const int bm = blockIdx.x;
    const int bn = blockIdx.y;
    const int rowBase = bm * 128;
    const int bRowBase = (MODE == 0) ? 0 : bn * 128;

    float* attnS = (float*)(smem + AOFF);
    float* sdot  = (float*)(smem + AOFF);
    float* accT  = (float*)(smem + TOFF);           // MODE 2: [64][256]

    if (MODE == 1) { if (tid < 128) sdot[tid] = 0.f; }
    if (MODE == 2) {
        for (int i = tid; i < 128 * NHEADS; i += 256)
            attnS[i] = aux[(size_t)(rowBase + (i >> 3)) * NHEADS + (i & 7)];
#pragma unroll
        for (int i = 0; i < 64; i++) accT[i * 256 + tid] = 0.f;
    }

    // per-thread copy slots: 4 chunks of 16B per tile, rows r0+32i, col c
    const int r0 = tid >> 3;            // 0..31
    const int c  = tid & 7;             // 0..7 (16B chunk within 128B data)
    size_t aOff[4], bOff[4];
    unsigned smA[4];
#pragma unroll
    for (int i = 0; i < 4; i++) {
        const int r = r0 + 32 * i;
        aOff[i] = ((size_t)(rowBase + r) * IN_DIM + c * 8) * 2;
        bOff[i] = ((size_t)(bRowBase + r) * IN_DIM + c * 8) * 2;
        smA[i]  = r * ROWB + c * 16;
    }

    auto LOAD = [&](int s, int bi) {
        if (s < NKT) {
            const unsigned sb = sbase + bi * BUFB;
            const size_t ka = (size_t)((s * KT) & (IN_DIM - 1)) * 2;
            const size_t kb = (MODE == 2)
                ? ka + (size_t)(s >> 4) * ((size_t)OUT_D * IN_DIM * 2) : ka;
#pragma unroll
            for (int i = 0; i < 4; i++) {
                CP16(sb + smA[i],          A16 + aOff[i] + ka);
                CP16(sb + TILE_B + smA[i], B16 + bOff[i] + kb);
            }
        }
        CP_COMMIT();
    };

    const int wm = (warp >> 2) * 64;
    const int wn = (warp & 3) * 32;
    const unsigned lrow  = lane & 15;
    const unsigned lcolB = (lane >> 4) * 16;

    float acc[4][4][4];
#pragma unroll
    for (int a = 0; a < 4; a++)
#pragma unroll
        for (int b = 0; b < 4; b++)
#pragma unroll
            for (int cc = 0; cc < 4; cc++) acc[a][b][cc] = 0.f;

    auto COMPUTE = [&](int bi) {
        const unsigned base = sbase + bi * BUFB;
#pragma unroll
        for (int ks = 0; ks < 4; ks++) {
            const unsigned kb = ks * 32 + lcolB;
            unsigned af[4][4], bf[2][4];
#pragma unroll
            for (int mf = 0; mf < 4; mf++) {
                unsigned ad = base + (wm + mf * 16 + lrow) * ROWB + kb;
                ldsm_x4(af[mf], ad);
            }
#pragma unroll
            for (int nf2 = 0; nf2 < 2; nf2++) {
                unsigned bd = base + TILE_B + (wn + nf2 * 16 + lrow) * ROWB + kb;
                ldsm_x4(bf[nf2], bd);
            }
#pragma unroll
            for (int mf = 0; mf < 4; mf++)
#pragma unroll
                for (int nf = 0; nf < 4; nf++) {
                    unsigned bh[2] = { bf[nf >> 1][nf & 1], bf[nf >> 1][(nf & 1) + 2] };
                    mma_f16(acc[mf][nf], af[mf], bh);
                }
        }
    };

    LOAD(0, 0); LOAD(1, 1);

    int bi = 0, li = 2;
    for (int s = 0; s < NKT; s++) {
        CP_WAIT1();
        __syncthreads();
        COMPUTE(bi);
        LOAD(s + 2, li);
        if (MODE == 2 && ((s & 15) == 15)) {
            const int h = s >> 4;
#pragma unroll
            for (int mf = 0; mf < 4; mf++)
#pragma unroll
                for (int eh = 0; eh < 2; eh++) {
                    const float sc = attnS[(wm + (lane >> 2) + mf * 16 + eh * 8) * NHEADS + h];
#pragma unroll
                    for (int nf = 0; nf < 4; nf++)
#pragma unroll
                        for (int e = 0; e < 2; e++) {
                            const int idx = mf * 16 + nf * 4 + eh * 2 + e;
                            accT[idx * 256 + tid] += sc * acc[mf][nf][eh * 2 + e];
                            acc[mf][nf][eh * 2 + e] = 0.f;
                        }
                }
        }
        bi = (bi == 2) ? 0 : bi + 1;
        li = (li == 2) ? 0 : li + 1;
    }

    // ---- epilogue ----
    const int erow0 = wm + (lane >> 2);
    const int ecol0 = wn + (lane & 3) * 2;

    if (MODE == 0) {
#pragma unroll
        for (int mf = 0; mf < 4; mf++)
#pragma unroll
            for (int e2 = 0; e2 < 2; e2++) {
                int r = rowBase + erow0 + mf * 16 + e2 * 8;
#pragma unroll
                for (int nf = 0; nf < 4; nf++) {
                    int cc = ecol0 + nf * 8;
                    float2 v;
                    v.x = acc[mf][nf][e2 * 2 + 0] + bias[cc];
                    v.y = acc[mf][nf][e2 * 2 + 1] + bias[cc + 1];
                    *(float2*)(out + (size_t)r * ATTN_D + cc) = v;
                }
            }
    } else if (MODE == 1) {
#pragma unroll
        for (int mf = 0; mf < 4; mf++)
#pragma unroll
            for (int e2 = 0; e2 < 2; e2++) {
                int rl = erow0 + mf * 16 + e2 * 8;
                int rg = rowBase + rl;
                float s = 0.f;
#pragma unroll
                for (int nf = 0; nf < 4; nf++) {
                    int cc = ecol0 + nf * 8;
                    float q0 = aux[(size_t)rg * ATTN_D + cc];
                    float q1 = aux[(size_t)rg * ATTN_D + cc + 1];
                    s += (acc[mf][nf][e2 * 2 + 0] + bias[bn * ATTN_D + cc])     * q0;
                    s += (acc[mf][nf][e2 * 2 + 1] + bias[bn * ATTN_D + cc + 1]) * q1;
                }
                atomicAdd(&sdot[rl], s);
            }
        __syncthreads();
        if (tid < 128)
            out[(size_t)(rowBase + tid) * NHEADS + bn] = sdot[tid];
    } else {
#pragma unroll
        for (int nf = 0; nf < 4; nf++) {
            int cc = bn * 128 + ecol0 + nf * 8;
            float bv0[NHEADS], bv1[NHEADS];
#pragma unroll
            for (int h = 0; h < NHEADS; h++) {
                bv0[h] = bias[h * OUT_D + cc];
                bv1[h] = bias[h * OUT_D + cc + 1];
            }
#pragma unroll
            for (int mf = 0; mf < 4; mf++)
#pragma unroll
                for (int e2 = 0; e2 < 2; e2++) {
                    int rl = erow0 + mf * 16 + e2 * 8;
                    int rg = rowBase + rl;
                    float b0 = 0.f, b1 = 0.f;
#pragma unroll
                    for (int h = 0; h < NHEADS; h++) {
                        float at = attnS[rl * NHEADS + h];
                        b0 += at * bv0[h];
                        b1 += at * bv1[h];
                    }
                    float2 v;
                    v.x = accT[(mf * 16 + nf * 4 + e2 * 2 + 0) * 256 + tid] + b0;
                    v.y = accT[(mf * 16 + nf * 4 + e2 * 2 + 1) * 256 + tid] + b1;
                    *(float2*)(out + (size_t)rg * OUT_D + cc) = v;
                }
        }
    }
}

__global__ void softmax_kernel(const float* __restrict__ dot, float* __restrict__ attn) {
    int b = blockIdx.x * blockDim.x + threadIdx.x;
    if (b >= BATCH_N) return;
    const float sc = 0.08838834764831845f;
    float d[NHEADS], m = -1e30f;
#pragma unroll
    for (int h = 0; h < NHEADS; h++) { d[h] = dot[b * NHEADS + h] * sc; m = fmaxf(m, d[h]); }
    float s = 0.f;
#pragma unroll
    for (int h = 0; h < NHEADS; h++) { d[h] = __expf(d[h] - m); s += d[h]; }
    float inv = 1.f / s;
#pragma unroll
    for (int h = 0; h < NHEADS; h++) attn[b * NHEADS + h] = d[h] * inv;
}

extern "C" void kernel_launch(void* const* d_in, const int* in_sizes, int n_in,
                              void* d_out, int out_size) {
    const float* x  = (const float*)d_in[0];
    const float* Wq = (const float*)d_in[1];
    const float* bq = (const float*)d_in[2];
    const float* Wk = (const float*)d_in[3];
    const float* bk = (const float*)d_in[4];
    const float* Wv = (const float*)d_in[5];
    const float* bv = (const float*)d_in[6];
    float* out = (float*)d_out;

    float *qp, *dp, *ap;
    cudaGetSymbolAddress((void**)&qp, g_q);
    cudaGetSymbolAddress((void**)&dp, g_dot);
    cudaGetSymbolAddress((void**)&ap, g_attn);
    uint2 *x16, *wq16, *wk16, *wv16;
    cudaGetSymbolAddress((void**)&x16,  g_x16);
    cudaGetSymbolAddress((void**)&wq16, g_wq16);
    cudaGetSymbolAddress((void**)&wk16, g_wk16);
    cudaGetSymbolAddress((void**)&wv16, g_wv16);

    cudaFuncSetAttribute(gemm_kernel<0, 16>,  cudaFuncAttributeMaxDynamicSharedMemorySize, SMEM_T01);
    cudaFuncSetAttribute(gemm_kernel<1, 16>,  cudaFuncAttributeMaxDynamicSharedMemorySize, SMEM_T01);
    cudaFuncSetAttribute(gemm_kernel<2, 128>, cudaFuncAttributeMaxDynamicSharedMemorySize, SMEM_T2);

    // pre-pass: fp32 -> fp16 conversions
    {
        int n4;
        n4 = BATCH_N * IN_DIM / 4;
        conv_f16_kernel<<<(n4 + 255) / 256, 256>>>((const float4*)x, x16, n4);
        n4 = ATTN_D * IN_DIM / 4;
        conv_f16_kernel<<<(n4 + 255) / 256, 256>>>((const float4*)Wq, wq16, n4);
        n4 = NHEADS * ATTN_D * IN_DIM / 4;
        conv_f16_kernel<<<(n4 + 255) / 256, 256>>>((const float4*)Wk, wk16, n4);
        n4 = (int)((size_t)NHEADS * OUT_D * IN_DIM / 4);
        conv_f16_kernel<<<(n4 + 255) / 256, 256>>>((const float4*)Wv, wv16, n4);
    }

    gemm_kernel<0, 16><<<dim3(BATCH_N / 128, 1), 256, SMEM_T01>>>(
        (const char*)x16, (const char*)wq16, bq, nullptr, qp);
    gemm_kernel<1, 16><<<dim3(BATCH_N / 128, NHEADS), 256, SMEM_T01>>>(
        (const char*)x16, (const char*)wk16, bk, qp, dp);
    softmax_kernel<<<BATCH_N / 256, 256>>>(dp, ap);
    gemm_kernel<2, 128><<<dim3(BATCH_N / 128, NHEADS), 256, SMEM_T2>>>(
        (const char*)x16, (const char*)wv16, bv, ap, out);
}